// round 3
// baseline (speedup 1.0000x reference)
#include <cuda_runtime.h>
#include <cuda_bf16.h>

// LocallyConnected1d: out[b,c,o] = sum_{ci,k} x[b,ci,4o+k] * w[c,ci,o,k] / sqrt(64)
// x: [128, 64, 1028] f32, w: [1, 64, 64, 256, 8] f32, out: [128, 64, 256] f32
// One CTA per output position o: SGEMM M=128(b) x N=64(c) x K=512(ci*8).

#define B_DIM   128
#define CIN     64
#define COUT    64
#define OUT_DIM 256
#define KW      8
#define STRIDE  4
#define L_DIM   1028   // (256-1)*4 + 8

#define BM 128
#define BN 64
#define BK 32
#define TM 8
#define TN 4
#define NTHREADS 256   // (BM/TM) * (BN/TN) = 16*16

__global__ __launch_bounds__(NTHREADS, 2)
void lc1d_kernel(const float* __restrict__ x,
                 const float* __restrict__ w,
                 float* __restrict__ out)
{
    const int o   = blockIdx.x;          // output position, 0..255
    const int tid = threadIdx.x;
    const int tx  = tid & 15;            // n tile index, 0..15
    const int ty  = tid >> 4;            // m tile index, 0..15

    __shared__ __align__(16) float As[BK][BM + 4];  // [kk][m], row stride 132 words
    __shared__ __align__(16) float Bs[BK][BN + 4];  // [kk][n], row stride 68 words

    float acc[TM][TN];
    #pragma unroll
    for (int i = 0; i < TM; i++)
        #pragma unroll
        for (int j = 0; j < TN; j++)
            acc[i][j] = 0.0f;

    const int xcol = o * STRIDE;         // leftmost x column for this o

    // K loop over CIN*KW = 512 in chunks of BK=32 (4 channels x 8 taps per chunk)
    for (int kt = 0; kt < CIN * KW; kt += BK) {
        const int cibase = kt >> 3;      // first channel of this chunk

        // ---- load A tile: 128 x 32 floats = 1024 float4, 4 per thread ----
        #pragma unroll
        for (int i = 0; i < 4; i++) {
            int idx4 = tid + i * NTHREADS;       // 0..1023
            int f    = idx4 & 7;                 // float4 index within row
            int m    = idx4 >> 3;                // 0..127 (batch)
            int ci   = cibase + (f >> 1);
            int k    = (f & 1) * 4;
            const float4 v = *reinterpret_cast<const float4*>(
                &x[(m * CIN + ci) * L_DIM + xcol + k]);
            int kk = f * 4;                      // (f>>1)*8 + (f&1)*4 == 4f
            As[kk + 0][m] = v.x;
            As[kk + 1][m] = v.y;
            As[kk + 2][m] = v.z;
            As[kk + 3][m] = v.w;
        }

        // ---- load B tile: 64 x 32 floats = 512 float4, 2 per thread ----
        #pragma unroll
        for (int i = 0; i < 2; i++) {
            int idx4 = tid + i * NTHREADS;       // 0..511
            int f    = idx4 & 7;
            int n    = idx4 >> 3;                // 0..63 (cout)
            int ci   = cibase + (f >> 1);
            int k    = (f & 1) * 4;
            const float4 v = *reinterpret_cast<const float4*>(
                &w[((n * CIN + ci) * OUT_DIM + o) * KW + k]);
            int kk = f * 4;
            Bs[kk + 0][n] = v.x;
            Bs[kk + 1][n] = v.y;
            Bs[kk + 2][n] = v.z;
            Bs[kk + 3][n] = v.w;
        }

        __syncthreads();

        // ---- compute ----
        #pragma unroll
        for (int k = 0; k < BK; k++) {
            float a[TM], b[TN];
            const float4 a0 = *reinterpret_cast<const float4*>(&As[k][ty * TM]);
            const float4 a1 = *reinterpret_cast<const float4*>(&As[k][ty * TM + 4]);
            const float4 bv = *reinterpret_cast<const float4*>(&Bs[k][tx * TN]);
            a[0] = a0.x; a[1] = a0.y; a[2] = a0.z; a[3] = a0.w;
            a[4] = a1.x; a[5] = a1.y; a[6] = a1.z; a[7] = a1.w;
            b[0] = bv.x; b[1] = bv.y; b[2] = bv.z; b[3] = bv.w;
            #pragma unroll
            for (int i = 0; i < TM; i++)
                #pragma unroll
                for (int j = 0; j < TN; j++)
                    acc[i][j] = fmaf(a[i], b[j], acc[i][j]);
        }

        __syncthreads();
    }

    // ---- epilogue: out[b, c, o] = acc * 1/sqrt(64) ----
    const float scale = 0.125f;
    #pragma unroll
    for (int i = 0; i < TM; i++) {
        int b = ty * TM + i;
        #pragma unroll
        for (int j = 0; j < TN; j++) {
            int c = tx * TN + j;
            out[(b * COUT + c) * OUT_DIM + o] = acc[i][j] * scale;
        }
    }
}

extern "C" void kernel_launch(void* const* d_in, const int* in_sizes, int n_in,
                              void* d_out, int out_size)
{
    const float* x = (const float*)d_in[0];   // [128, 64, 1028]
    const float* w = (const float*)d_in[1];   // [1, 64, 64, 256, 8]
    float* out = (float*)d_out;               // [128, 64, 256]
    (void)in_sizes; (void)n_in; (void)out_size;

    lc1d_kernel<<<OUT_DIM, NTHREADS>>>(x, w, out);
}

// round 4
// speedup vs baseline: 1.1442x; 1.1442x over previous
#include <cuda_runtime.h>
#include <cuda_bf16.h>

// LocallyConnected1d: out[b,c,o] = sum_{ci,k} x[b,ci,4o+k] * w[c,ci,o,k] / 8
// x: [128, 64, 1028] f32, w: [64, 64, 256, 8] f32, out: [128, 64, 256] f32
// One CTA per o: SGEMM M=128(b) x N=64(c) x K=512(ci*8).
// Swizzled smem (conflict-free transpose stores), double-buffered tiles,
// fragment double-buffering, one barrier per tile.

#define CIN     64
#define COUT    64
#define OUT_DIM 256
#define KW      8
#define L_DIM   1028

#define BM 128
#define BN 64
#define BK 32
#define NTHREADS 256
#define NTILES 16           // 512 / BK

__global__ __launch_bounds__(NTHREADS, 2)
void lc1d_kernel(const float* __restrict__ x,
                 const float* __restrict__ w,
                 float* __restrict__ out)
{
    const int o   = blockIdx.x;
    const int tid = threadIdx.x;
    const int tx  = tid & 15;           // n tile index
    const int ty  = tid >> 4;           // m tile index

    // Swizzled layout: element (k, col) lives at
    //   [k][ (((col>>2) ^ ((k>>2)&7)) << 2) | (col&3) ]
    // No padding needed; stores and frag loads are conflict-free.
    __shared__ __align__(16) float As[2][BK][BM];
    __shared__ __align__(16) float Bs[2][BK][BN];

    float acc[8][4];
    #pragma unroll
    for (int i = 0; i < 8; i++)
        #pragma unroll
        for (int j = 0; j < 4; j++)
            acc[i][j] = 0.0f;

    const int xcol = o * 4;

    // Global-load geometry: thread owns float4 #fA of each k-row.
    const int fA  = tid & 7;            // 0..7 ; ci_off = fA>>1, tap = (fA&1)*4
    const int kkA = fA << 2;            // base k-row for this thread's stores
    const int ciOff = fA >> 1;
    const int ktap  = (fA & 1) << 2;

    float4 va[4], vb[2];

    // ---- global load of tile t into registers ----
    #define LDG_TILE(t)                                                        \
        do {                                                                   \
            const int ci = ((t) << 2) + ciOff;                                 \
            _Pragma("unroll")                                                  \
            for (int i = 0; i < 4; i++) {                                      \
                int m = (tid + i * NTHREADS) >> 3;                             \
                va[i] = *reinterpret_cast<const float4*>(                      \
                    &x[(m * CIN + ci) * L_DIM + xcol + ktap]);                 \
            }                                                                  \
            _Pragma("unroll")                                                  \
            for (int i = 0; i < 2; i++) {                                      \
                int n = (tid + i * NTHREADS) >> 3;                             \
                vb[i] = *reinterpret_cast<const float4*>(                      \
                    &w[((n * CIN + ci) * OUT_DIM + o) * KW + ktap]);           \
            }                                                                  \
        } while (0)

    // ---- store staged registers into smem buffer (swizzled, conflict-free) ----
    #define STS_TILE(buf)                                                      \
        do {                                                                   \
            _Pragma("unroll")                                                  \
            for (int i = 0; i < 4; i++) {                                      \
                int m = (tid + i * NTHREADS) >> 3;                             \
                int col = (((m >> 2) ^ fA) << 2) | (m & 3);                    \
                As[buf][kkA + 0][col] = va[i].x;                               \
                As[buf][kkA + 1][col] = va[i].y;                               \
                As[buf][kkA + 2][col] = va[i].z;                               \
                As[buf][kkA + 3][col] = va[i].w;                               \
            }                                                                  \
            _Pragma("unroll")                                                  \
            for (int i = 0; i < 2; i++) {                                      \
                int n = (tid + i * NTHREADS) >> 3;                             \
                int col = (((n >> 2) ^ fA) << 2) | (n & 3);                    \
                Bs[buf][kkA + 0][col] = vb[i].x;                               \
                Bs[buf][kkA + 1][col] = vb[i].y;                               \
                Bs[buf][kkA + 2][col] = vb[i].z;                               \
                Bs[buf][kkA + 3][col] = vb[i].w;                               \
            }                                                                  \
        } while (0)

    // ---- load register fragments for k-step k from buffer buf ----
    #define LDFRAG(k, slot, buf)                                               \
        do {                                                                   \
            const int fk = ((k) >> 2) & 7;                                     \
            a0[slot] = *reinterpret_cast<const float4*>(                       \
                &As[buf][k][((2 * ty) ^ fk) << 2]);                            \
            a1[slot] = *reinterpret_cast<const float4*>(                       \
                &As[buf][k][((2 * ty + 1) ^ fk) << 2]);                        \
            b0[slot] = *reinterpret_cast<const float4*>(                       \
                &Bs[buf][k][(tx ^ fk) << 2]);                                  \
        } while (0)

    // prologue
    LDG_TILE(0);
    STS_TILE(0);
    __syncthreads();

    for (int t = 0; t < NTILES; t++) {
        const int cur = t & 1;
        if (t + 1 < NTILES) LDG_TILE(t + 1);

        float4 a0[2], a1[2], b0[2];
        LDFRAG(0, 0, cur);

        #pragma unroll
        for (int k = 0; k < BK; k++) {
            const int cs = k & 1;
            if (k + 1 < BK) LDFRAG(k + 1, cs ^ 1, cur);

            float a[8], b[4];
            a[0] = a0[cs].x; a[1] = a0[cs].y; a[2] = a0[cs].z; a[3] = a0[cs].w;
            a[4] = a1[cs].x; a[5] = a1[cs].y; a[6] = a1[cs].z; a[7] = a1[cs].w;
            b[0] = b0[cs].x; b[1] = b0[cs].y; b[2] = b0[cs].z; b[3] = b0[cs].w;
            #pragma unroll
            for (int i = 0; i < 8; i++)
                #pragma unroll
                for (int j = 0; j < 4; j++)
                    acc[i][j] = fmaf(a[i], b[j], acc[i][j]);
        }

        if (t + 1 < NTILES) STS_TILE(cur ^ 1);
        __syncthreads();
    }

    // epilogue: out[b, c, o] = acc / sqrt(64)
    const float scale = 0.125f;
    #pragma unroll
    for (int i = 0; i < 8; i++) {
        int b = ty * 8 + i;
        #pragma unroll
        for (int j = 0; j < 4; j++) {
            int c = tx * 4 + j;
            out[(b * COUT + c) * OUT_DIM + o] = acc[i][j] * scale;
        }
    }
}

extern "C" void kernel_launch(void* const* d_in, const int* in_sizes, int n_in,
                              void* d_out, int out_size)
{
    const float* x = (const float*)d_in[0];   // [128, 64, 1028]
    const float* w = (const float*)d_in[1];   // [1, 64, 64, 256, 8]
    float* out = (float*)d_out;               // [128, 64, 256]
    (void)in_sizes; (void)n_in; (void)out_size;

    lc1d_kernel<<<OUT_DIM, NTHREADS>>>(x, w, out);
}

// round 8
// speedup vs baseline: 1.3630x; 1.1912x over previous
#include <cuda_runtime.h>
#include <cuda_bf16.h>
#include <cstdint>

// LocallyConnected1d via portable HMMA (mma.sync bf16, sm_80+ PTX — no 'a' features).
// out[b,c,o] = sum_{ci,k} x[b,ci,4o+k] * w[c,ci,o,k] / 8
// One CTA per o: D[128,64] = A[128,512] @ B[64,512]^T  (K = ci*8)
// fp32 -> bf16 hi/lo split: D = Ah*Bh + Ah*Bl + Al*Bh, fp32 accum in registers.

#define CIN     64
#define COUT    64
#define OUT_DIM 256
#define KW      8
#define L_DIM   1028

#define NTHREADS 256        // 8 warps: 4 along M x 2 along N, warp tile 32x32
#define KBLK     64         // bf16 K per tile = 128 bytes per row
#define NBLK     8          // 512 / 64

// per-buffer smem layout (bytes); rows are 128B, XOR-16B swizzled
#define A_HI 0              // 128 rows * 128B = 16KB
#define A_LO 16384
#define B_HI 32768          // 64 rows * 128B = 8KB
#define B_LO 40960
#define BUF_BYTES 49152
#define SMEM_TOTAL (2 * BUF_BYTES)   // 96KB dynamic

#define SWZ(off) ((off) ^ (((off) >> 3) & 0x70))   // 16B-granule swizzle within 128B row

__device__ __forceinline__ uint32_t smem_u32(const void* p) {
    uint32_t a;
    asm("{ .reg .u64 t; cvta.to.shared.u64 t, %1; cvt.u32.u64 %0, t; }" : "=r"(a) : "l"(p));
    return a;
}

__device__ __forceinline__ void ldsm4(uint32_t* r, uint32_t addr) {
    asm volatile("ldmatrix.sync.aligned.m8n8.x4.shared.b16 {%0,%1,%2,%3}, [%4];"
                 : "=r"(r[0]), "=r"(r[1]), "=r"(r[2]), "=r"(r[3]) : "r"(addr));
}

__device__ __forceinline__ void mma16816(float* d, const uint32_t* a, const uint32_t* b) {
    asm volatile(
        "mma.sync.aligned.m16n8k16.row.col.f32.bf16.bf16.f32 "
        "{%0,%1,%2,%3}, {%4,%5,%6,%7}, {%8,%9}, {%0,%1,%2,%3};"
        : "+f"(d[0]), "+f"(d[1]), "+f"(d[2]), "+f"(d[3])
        : "r"(a[0]), "r"(a[1]), "r"(a[2]), "r"(a[3]), "r"(b[0]), "r"(b[1]));
}

// split float4 into hi/lo bf16x4 (each packed as uint2, memory order x,y,z,w)
__device__ __forceinline__ void cvt4(float4 v, uint2& hi, uint2& lo) {
    __nv_bfloat162 h01 = __floats2bfloat162_rn(v.x, v.y);
    __nv_bfloat162 h23 = __floats2bfloat162_rn(v.z, v.w);
    float r0 = v.x - __bfloat162float(__low2bfloat16(h01));
    float r1 = v.y - __bfloat162float(__high2bfloat16(h01));
    float r2 = v.z - __bfloat162float(__low2bfloat16(h23));
    float r3 = v.w - __bfloat162float(__high2bfloat16(h23));
    __nv_bfloat162 l01 = __floats2bfloat162_rn(r0, r1);
    __nv_bfloat162 l23 = __floats2bfloat162_rn(r2, r3);
    hi.x = *reinterpret_cast<uint32_t*>(&h01);
    hi.y = *reinterpret_cast<uint32_t*>(&h23);
    lo.x = *reinterpret_cast<uint32_t*>(&l01);
    lo.y = *reinterpret_cast<uint32_t*>(&l23);
}

__global__ void __launch_bounds__(NTHREADS, 1)
lc1d_hmma(const float* __restrict__ x,
          const float* __restrict__ w,
          float* __restrict__ out)
{
    extern __shared__ char smem[];
    const uint32_t sbase = smem_u32(smem);
    const int tid = threadIdx.x;
    const int wid = tid >> 5;
    const int lid = tid & 31;
    const int o   = blockIdx.x;

    // ---------------- loader geometry (fp32 -> bf16 hi/lo, swizzled STS) ----
    const int am = tid >> 1;          // A row (batch) 0..127
    const int ahp = tid & 1;          // owns float4s [ahp*8, ahp*8+8) of the row
    const int bc = tid >> 2;          // B row (cout) 0..63
    const int bq = tid & 3;           // owns float4s [bq*4, bq*4+4)
    const int xcol = 4 * o;

    float4 va[8], vb[4];

    #define LDG_BLK(t)                                                         \
        do {                                                                   \
            const int cib = (t) * 8;                                           \
            _Pragma("unroll")                                                  \
            for (int i = 0; i < 8; i++) {                                      \
                int f4 = ahp * 8 + i;                                          \
                int ci = cib + (f4 >> 1);                                      \
                int tap = (f4 & 1) * 4;                                        \
                va[i] = *reinterpret_cast<const float4*>(                      \
                    &x[(am * CIN + ci) * L_DIM + xcol + tap]);                 \
            }                                                                  \
            _Pragma("unroll")                                                  \
            for (int i = 0; i < 4; i++) {                                      \
                int f4 = bq * 4 + i;                                           \
                int ci = cib + (f4 >> 1);                                      \
                int tap = (f4 & 1) * 4;                                        \
                vb[i] = *reinterpret_cast<const float4*>(                      \
                    &w[((bc * CIN + ci) * OUT_DIM + o) * KW + tap]);           \
            }                                                                  \
        } while (0)

    #define STS_BLK(buf)                                                       \
        do {                                                                   \
            char* tb = smem + (buf) * BUF_BYTES;                               \
            _Pragma("unroll")                                                  \
            for (int i = 0; i < 8; i++) {                                      \
                int f4 = ahp * 8 + i;                                          \
                uint2 hi, lo;                                                  \
                cvt4(va[i], hi, lo);                                           \
                uint32_t off = SWZ((uint32_t)(am * 128 + f4 * 8));             \
                *reinterpret_cast<uint2*>(tb + A_HI + off) = hi;               \
                *reinterpret_cast<uint2*>(tb + A_LO + off) = lo;               \
            }                                                                  \
            _Pragma("unroll")                                                  \
            for (int i = 0; i < 4; i++) {                                      \
                int f4 = bq * 4 + i;                                           \
                uint2 hi, lo;                                                  \
                cvt4(vb[i], hi, lo);                                           \
                uint32_t off = SWZ((uint32_t)(bc * 128 + f4 * 8));             \
                *reinterpret_cast<uint2*>(tb + B_HI + off) = hi;               \
                *reinterpret_cast<uint2*>(tb + B_LO + off) = lo;               \
            }                                                                  \
        } while (0)

    // ---------------- mma geometry -----------------------------------------
    const int mw = wid >> 1;          // 0..3 -> m0 = mw*32
    const int nw = wid & 1;           // 0..1 -> n0 = nw*32
    const int m0 = mw * 32;
    const int n0 = nw * 32;
    const int sub = lid >> 3;         // ldmatrix sub-matrix index 0..3
    const int r8  = lid & 7;

    // A x4 recipe (per mi tile, m16 x k16): rows m0+mi*16+(sub&1)*8+r8, k half = (sub>>1)
    const int arow0 = m0 + (sub & 1) * 8 + r8;
    const int kbA   = (sub >> 1) * 16;
    // B x4 recipe (per bj pair, covers n-tiles 2bj,2bj+1): rows n0+bj*16+(sub>>1)*8+r8,
    // k half = (sub&1)
    const int brow0 = n0 + (sub >> 1) * 8 + r8;
    const int kbB   = (sub & 1) * 16;

    float acc[2][4][4];
    #pragma unroll
    for (int i = 0; i < 2; i++)
        #pragma unroll
        for (int j = 0; j < 4; j++)
            #pragma unroll
            for (int q = 0; q < 4; q++)
                acc[i][j][q] = 0.0f;

    // ---------------- pipeline ---------------------------------------------
    LDG_BLK(0);
    STS_BLK(0);
    __syncthreads();

    for (int t = 0; t < NBLK; t++) {
        if (t + 1 < NBLK) LDG_BLK(t + 1);

        const uint32_t bufb = sbase + (uint32_t)(t & 1) * BUF_BYTES;

        #pragma unroll
        for (int ks = 0; ks < 4; ks++) {
            const int kb = ks * 32;
            uint32_t ah[8], al[8], bh[8], bl[8];

            #pragma unroll
            for (int mi = 0; mi < 2; mi++) {
                int row = arow0 + mi * 16;
                uint32_t ad = bufb + A_HI + row * 128 + ((kb + kbA) ^ ((row & 7) << 4));
                ldsm4(&ah[mi * 4], ad);
                ldsm4(&al[mi * 4], ad + (A_LO - A_HI));
            }
            #pragma unroll
            for (int bj = 0; bj < 2; bj++) {
                int row = brow0 + bj * 16;
                uint32_t bd = bufb + B_HI + row * 128 + ((kb + kbB) ^ ((row & 7) << 4));
                ldsm4(&bh[bj * 4], bd);
                ldsm4(&bl[bj * 4], bd + (B_LO - B_HI));
            }

            #pragma unroll
            for (int mi = 0; mi < 2; mi++)
                #pragma unroll
                for (int nj = 0; nj < 4; nj++) {
                    mma16816(acc[mi][nj], &ah[mi * 4], &bh[nj * 2]);
                    mma16816(acc[mi][nj], &ah[mi * 4], &bl[nj * 2]);
                    mma16816(acc[mi][nj], &al[mi * 4], &bh[nj * 2]);
                }
        }

        if (t + 1 < NBLK) {
            STS_BLK((t + 1) & 1);
            __syncthreads();
        }
    }

    // ---------------- epilogue ----------------------------------------------
    const float s = 0.125f;
    const int g = lid >> 2;          // row within 8
    const int tq = lid & 3;          // col pair
    #pragma unroll
    for (int mi = 0; mi < 2; mi++) {
        #pragma unroll
        for (int nj = 0; nj < 4; nj++) {
            int r0 = m0 + mi * 16 + g;
            int c0 = n0 + nj * 8 + 2 * tq;
            out[((r0    ) * COUT + c0    ) * OUT_DIM + o] = acc[mi][nj][0] * s;
            out[((r0    ) * COUT + c0 + 1) * OUT_DIM + o] = acc[mi][nj][1] * s;
            out[((r0 + 8) * COUT + c0    ) * OUT_DIM + o] = acc[mi][nj][2] * s;
            out[((r0 + 8) * COUT + c0 + 1) * OUT_DIM + o] = acc[mi][nj][3] * s;
        }
    }
}

extern "C" void kernel_launch(void* const* d_in, const int* in_sizes, int n_in,
                              void* d_out, int out_size)
{
    const float* x = (const float*)d_in[0];   // [128, 64, 1028]
    const float* w = (const float*)d_in[1];   // [1, 64, 64, 256, 8]
    float* out = (float*)d_out;               // [128, 64, 256]
    (void)in_sizes; (void)n_in; (void)out_size;

    cudaFuncSetAttribute(lc1d_hmma, cudaFuncAttributeMaxDynamicSharedMemorySize,
                         SMEM_TOTAL);
    lc1d_hmma<<<OUT_DIM, NTHREADS, SMEM_TOTAL>>>(x, w, out);
}

// round 9
// speedup vs baseline: 1.3823x; 1.0141x over previous
#include <cuda_runtime.h>
#include <cuda_bf16.h>
#include <cstdint>

// LocallyConnected1d via portable HMMA (mma.sync bf16, sm_80+ PTX).
// out[b,c,o] = sum_{ci,k} x[b,ci,4o+k] * w[c,ci,o,k] / 8
// One CTA per o: D[128,64] = A[128,512] @ B[64,512]^T  (K = ci*8)
// fp32 -> bf16 hi/lo split: D = Ah*Bh + Ah*Bl + Al*Bh, fp32 accum in registers.
// R9: single smem buffer + __launch_bounds__(256,2) -> 2 CTAs/SM, 1 wave.

#define CIN     64
#define COUT    64
#define OUT_DIM 256
#define KW      8
#define L_DIM   1028

#define NTHREADS 256        // 8 warps: 4 along M x 2 along N, warp tile 32x32
#define KBLK     64         // bf16 K per tile = 128 bytes per row
#define NBLK     8          // 512 / 64

// smem layout (bytes); rows are 128B, XOR-16B swizzled
#define A_HI 0              // 128 rows * 128B = 16KB
#define A_LO 16384
#define B_HI 32768          // 64 rows * 128B = 8KB
#define B_LO 40960
#define SMEM_TOTAL 49152    // 48KB -> 2 CTAs/SM

#define SWZ(off) ((off) ^ (((off) >> 3) & 0x70))   // 16B-granule swizzle within 128B row

__device__ __forceinline__ uint32_t smem_u32(const void* p) {
    uint32_t a;
    asm("{ .reg .u64 t; cvta.to.shared.u64 t, %1; cvt.u32.u64 %0, t; }" : "=r"(a) : "l"(p));
    return a;
}

__device__ __forceinline__ void ldsm4(uint32_t* r, uint32_t addr) {
    asm volatile("ldmatrix.sync.aligned.m8n8.x4.shared.b16 {%0,%1,%2,%3}, [%4];"
                 : "=r"(r[0]), "=r"(r[1]), "=r"(r[2]), "=r"(r[3]) : "r"(addr));
}

__device__ __forceinline__ void mma16816(float* d, const uint32_t* a, const uint32_t* b) {
    asm volatile(
        "mma.sync.aligned.m16n8k16.row.col.f32.bf16.bf16.f32 "
        "{%0,%1,%2,%3}, {%4,%5,%6,%7}, {%8,%9}, {%0,%1,%2,%3};"
        : "+f"(d[0]), "+f"(d[1]), "+f"(d[2]), "+f"(d[3])
        : "r"(a[0]), "r"(a[1]), "r"(a[2]), "r"(a[3]), "r"(b[0]), "r"(b[1]));
}

// split float4 into hi/lo bf16x4 (each packed as uint2, memory order x,y,z,w)
__device__ __forceinline__ void cvt4(float4 v, uint2& hi, uint2& lo) {
    __nv_bfloat162 h01 = __floats2bfloat162_rn(v.x, v.y);
    __nv_bfloat162 h23 = __floats2bfloat162_rn(v.z, v.w);
    float r0 = v.x - __bfloat162float(__low2bfloat16(h01));
    float r1 = v.y - __bfloat162float(__high2bfloat16(h01));
    float r2 = v.z - __bfloat162float(__low2bfloat16(h23));
    float r3 = v.w - __bfloat162float(__high2bfloat16(h23));
    __nv_bfloat162 l01 = __floats2bfloat162_rn(r0, r1);
    __nv_bfloat162 l23 = __floats2bfloat162_rn(r2, r3);
    hi.x = *reinterpret_cast<uint32_t*>(&h01);
    hi.y = *reinterpret_cast<uint32_t*>(&h23);
    lo.x = *reinterpret_cast<uint32_t*>(&l01);
    lo.y = *reinterpret_cast<uint32_t*>(&l23);
}

__global__ void __launch_bounds__(NTHREADS, 2)
lc1d_hmma(const float* __restrict__ x,
          const float* __restrict__ w,
          float* __restrict__ out)
{
    extern __shared__ char smem[];
    const uint32_t sbase = smem_u32(smem);
    const int tid = threadIdx.x;
    const int wid = tid >> 5;
    const int lid = tid & 31;
    const int o   = blockIdx.x;

    // ---------------- loader geometry (fp32 -> bf16 hi/lo, swizzled STS) ----
    const int am = tid >> 1;          // A row (batch) 0..127
    const int ahp = tid & 1;          // owns float4s [ahp*8, ahp*8+8) of the row
    const int bc = tid >> 2;          // B row (cout) 0..63
    const int bq = tid & 3;           // owns float4s [bq*4, bq*4+4)
    const int xcol = 4 * o;

    // ---------------- mma geometry -----------------------------------------
    const int mw = wid >> 1;          // 0..3 -> m0 = mw*32
    const int nw = wid & 1;           // 0..1 -> n0 = nw*32
    const int m0 = mw * 32;
    const int n0 = nw * 32;
    const int sub = lid >> 3;         // ldmatrix sub-matrix index 0..3
    const int r8  = lid & 7;

    // A x4 recipe (per mi tile, m16 x k16): rows m0+mi*16+(sub&1)*8+r8, k half = (sub>>1)
    const int arow0 = m0 + (sub & 1) * 8 + r8;
    const int kbA   = (sub >> 1) * 16;
    // B x4 recipe (per bj pair): rows n0+bj*16+(sub>>1)*8+r8, k half = (sub&1)
    const int brow0 = n0 + (sub >> 1) * 8 + r8;
    const int kbB   = (sub & 1) * 16;

    float acc[2][4][4];
    #pragma unroll
    for (int i = 0; i < 2; i++)
        #pragma unroll
        for (int j = 0; j < 4; j++)
            #pragma unroll
            for (int q = 0; q < 4; q++)
                acc[i][j][q] = 0.0f;

    for (int t = 0; t < NBLK; t++) {
        // ---- load phase: 12 LDG.128 batched, then cvt + swizzled STS ----
        {
            const int cib = t * 8;
            float4 va[8], vb[4];
            #pragma unroll
            for (int i = 0; i < 8; i++) {
                int f4 = ahp * 8 + i;
                int ci = cib + (f4 >> 1);
                int tap = (f4 & 1) * 4;
                va[i] = *reinterpret_cast<const float4*>(
                    &x[(am * CIN + ci) * L_DIM + xcol + tap]);
            }
            #pragma unroll
            for (int i = 0; i < 4; i++) {
                int f4 = bq * 4 + i;
                int ci = cib + (f4 >> 1);
                int tap = (f4 & 1) * 4;
                vb[i] = *reinterpret_cast<const float4*>(
                    &w[((bc * CIN + ci) * OUT_DIM + o) * KW + tap]);
            }
            #pragma unroll
            for (int i = 0; i < 8; i++) {
                int f4 = ahp * 8 + i;
                uint2 hi, lo;
                cvt4(va[i], hi, lo);
                uint32_t off = SWZ((uint32_t)(am * 128 + f4 * 8));
                *reinterpret_cast<uint2*>(smem + A_HI + off) = hi;
                *reinterpret_cast<uint2*>(smem + A_LO + off) = lo;
            }
            #pragma unroll
            for (int i = 0; i < 4; i++) {
                int f4 = bq * 4 + i;
                uint2 hi, lo;
                cvt4(vb[i], hi, lo);
                uint32_t off = SWZ((uint32_t)(bc * 128 + f4 * 8));
                *reinterpret_cast<uint2*>(smem + B_HI + off) = hi;
                *reinterpret_cast<uint2*>(smem + B_LO + off) = lo;
            }
        }
        __syncthreads();

        // ---- mma phase ----
        #pragma unroll
        for (int ks = 0; ks < 4; ks++) {
            const int kb = ks * 32;
            uint32_t ah[8], al[8], bh[8], bl[8];

            #pragma unroll
            for (int mi = 0; mi < 2; mi++) {
                int row = arow0 + mi * 16;
                uint32_t ad = sbase + A_HI + row * 128 + ((kb + kbA) ^ ((row & 7) << 4));
                ldsm4(&ah[mi * 4], ad);
                ldsm4(&al[mi * 4], ad + (A_LO - A_HI));
            }
            #pragma unroll
            for (int bj = 0; bj < 2; bj++) {
                int row = brow0 + bj * 16;
                uint32_t bd = sbase + B_HI + row * 128 + ((kb + kbB) ^ ((row & 7) << 4));
                ldsm4(&bh[bj * 4], bd);
                ldsm4(&bl[bj * 4], bd + (B_LO - B_HI));
            }

            #pragma unroll
            for (int mi = 0; mi < 2; mi++)
                #pragma unroll
                for (int nj = 0; nj < 4; nj++) {
                    mma16816(acc[mi][nj], &ah[mi * 4], &bh[nj * 2]);
                    mma16816(acc[mi][nj], &ah[mi * 4], &bl[nj * 2]);
                    mma16816(acc[mi][nj], &al[mi * 4], &bh[nj * 2]);
                }
        }
        __syncthreads();
    }

    // ---------------- epilogue ----------------------------------------------
    const float s = 0.125f;
    const int g = lid >> 2;          // row within 8
    const int tq = lid & 3;          // col pair
    #pragma unroll
    for (int mi = 0; mi < 2; mi++) {
        #pragma unroll
        for (int nj = 0; nj < 4; nj++) {
            int r0 = m0 + mi * 16 + g;
            int c0 = n0 + nj * 8 + 2 * tq;
            out[((r0    ) * COUT + c0    ) * OUT_DIM + o] = acc[mi][nj][0] * s;
            out[((r0    ) * COUT + c0 + 1) * OUT_DIM + o] = acc[mi][nj][1] * s;
            out[((r0 + 8) * COUT + c0    ) * OUT_DIM + o] = acc[mi][nj][2] * s;
            out[((r0 + 8) * COUT + c0 + 1) * OUT_DIM + o] = acc[mi][nj][3] * s;
        }
    }
}

extern "C" void kernel_launch(void* const* d_in, const int* in_sizes, int n_in,
                              void* d_out, int out_size)
{
    const float* x = (const float*)d_in[0];   // [128, 64, 1028]
    const float* w = (const float*)d_in[1];   // [1, 64, 64, 256, 8]
    float* out = (float*)d_out;               // [128, 64, 256]
    (void)in_sizes; (void)n_in; (void)out_size;

    cudaFuncSetAttribute(lc1d_hmma, cudaFuncAttributeMaxDynamicSharedMemorySize,
                         SMEM_TOTAL);
    lc1d_hmma<<<OUT_DIM, NTHREADS, SMEM_TOTAL>>>(x, w, out);
}

// round 14
// speedup vs baseline: 1.6781x; 1.2140x over previous
#include <cuda_runtime.h>
#include <cuda_bf16.h>
#include <cstdint>

// LocallyConnected1d via TF32 mma.sync + cp.async (all plain sm_80 PTX).
// out[b,c,o] = sum_{ci,k} x[b,ci,4o+k] * w[c,ci,o,k] / 8
// One CTA per o: D[128,64] = A[128,512] @ B[64,512]^T  (K = ci*8)
// fp32 tiles staged GMEM->SMEM via cp.async (no reg round-trip, no pre-cvt);
// fragments loaded via scalar LDS then cvt.rna.tf32; single tf32 GEMM.

#define CIN     64
#define COUT    64
#define OUT_DIM 256
#define KW      8
#define L_DIM   1028

#define NTHREADS 256        // 8 warps: 4 along M x 2 along N, warp tile 32x32
#define KBLK     32         // fp32 K per tile (4 ci x 8 taps)
#define NBLK     16         // 512 / 32

// padded rows: 32 data words + 4 pad = 36 words = 144B (16B-aligned, LDS conflict-free)
#define ROW_B    144
#define A_BYTES  (128 * ROW_B)   // 18432
#define B_BYTES  (64 * ROW_B)    // 9216
#define STAGE_BYTES (A_BYTES + B_BYTES)   // 27648
#define SMEM_TOTAL  (2 * STAGE_BYTES)     // 55296 -> 2 CTAs/SM

__device__ __forceinline__ uint32_t smem_u32(const void* p) {
    uint32_t a;
    asm("{ .reg .u64 t; cvta.to.shared.u64 t, %1; cvt.u32.u64 %0, t; }" : "=r"(a) : "l"(p));
    return a;
}

__device__ __forceinline__ uint32_t lds_tf32(uint32_t addr) {
    float f;
    asm("ld.shared.f32 %0, [%1];" : "=f"(f) : "r"(addr));
    uint32_t t;
    asm("cvt.rna.tf32.f32 %0, %1;" : "=r"(t) : "f"(f));
    return t;
}

__device__ __forceinline__ void mma_tf32(float* d, const uint32_t* a, const uint32_t* b) {
    asm volatile(
        "mma.sync.aligned.m16n8k8.row.col.f32.tf32.tf32.f32 "
        "{%0,%1,%2,%3}, {%4,%5,%6,%7}, {%8,%9}, {%0,%1,%2,%3};"
        : "+f"(d[0]), "+f"(d[1]), "+f"(d[2]), "+f"(d[3])
        : "r"(a[0]), "r"(a[1]), "r"(a[2]), "r"(a[3]), "r"(b[0]), "r"(b[1]));
}

__device__ __forceinline__ void cp16(uint32_t dst, const void* src) {
    asm volatile("cp.async.cg.shared.global [%0], [%1], 16;" :: "r"(dst), "l"(src));
}

__global__ void __launch_bounds__(NTHREADS, 2)
lc1d_tf32(const float* __restrict__ x,
          const float* __restrict__ w,
          float* __restrict__ out)
{
    extern __shared__ char smem[];
    const uint32_t sbase = smem_u32(smem);
    const int tid = threadIdx.x;
    const int wid = tid >> 5;
    const int lid = tid & 31;
    const int o   = blockIdx.x;
    const int xcol = 4 * o;

    // mma geometry: 4 m-warps x 2 n-warps, warp tile 32x32
    const int m0 = (wid >> 1) * 32;
    const int n0 = (wid & 1) * 32;
    const int g  = lid >> 2;          // 0..7
    const int tq = lid & 3;           // 0..3

    float acc[2][4][4];
    #pragma unroll
    for (int i = 0; i < 2; i++)
        #pragma unroll
        for (int j = 0; j < 4; j++)
            #pragma unroll
            for (int q = 0; q < 4; q++)
                acc[i][j][q] = 0.0f;

    // ---- cp.async stage issue: tile t (ci in [4t, 4t+4)) into buffer buf ----
    #define CP_ISSUE(t, buf)                                                   \
        do {                                                                   \
            const int cib = (t) * 4;                                           \
            const uint32_t sb = sbase + (uint32_t)(buf) * STAGE_BYTES;         \
            _Pragma("unroll")                                                  \
            for (int i = 0; i < 4; i++) {          /* A: 1024 x 16B */         \
                int idx  = i * 256 + tid;                                      \
                int m    = idx >> 3;                                           \
                int ci   = (idx >> 1) & 3;                                     \
                int half = idx & 1;                                            \
                cp16(sb + m * ROW_B + ci * 32 + half * 16,                     \
                     &x[(m * CIN + cib + ci) * L_DIM + xcol + half * 4]);      \
            }                                                                  \
            _Pragma("unroll")                                                  \
            for (int i = 0; i < 2; i++) {          /* B: 512 x 16B */          \
                int idx  = i * 256 + tid;                                      \
                int c    = idx >> 3;                                           \
                int ci   = (idx >> 1) & 3;                                     \
                int half = idx & 1;                                            \
                cp16(sb + A_BYTES + c * ROW_B + ci * 32 + half * 16,           \
                     &w[((c * CIN + cib + ci) * OUT_DIM + o) * KW + half * 4]);\
            }                                                                  \
            asm volatile("cp.async.commit_group;" ::: "memory");               \
        } while (0)

    // prologue: 2 stages in flight
    CP_ISSUE(0, 0);
    CP_ISSUE(1, 1);

    for (int t = 0; t < NBLK; t++) {
        if (t < NBLK - 1)
            asm volatile("cp.async.wait_group 1;" ::: "memory");
        else
            asm volatile("cp.async.wait_group 0;" ::: "memory");
        __syncthreads();

        const uint32_t ab = sbase + (uint32_t)(t & 1) * STAGE_BYTES;
        const uint32_t bb = ab + A_BYTES;

        #pragma unroll
        for (int ks = 0; ks < 4; ks++) {
            const int kb = ks * 8;
            uint32_t Af[2][4], Bf[4][2];

            #pragma unroll
            for (int mi = 0; mi < 2; mi++) {
                uint32_t base = ab + (m0 + mi * 16 + g) * ROW_B + (kb + tq) * 4;
                Af[mi][0] = lds_tf32(base);
                Af[mi][1] = lds_tf32(base + 8 * ROW_B);
                Af[mi][2] = lds_tf32(base + 16);
                Af[mi][3] = lds_tf32(base + 8 * ROW_B + 16);
            }
            #pragma unroll
            for (int nj = 0; nj < 4; nj++) {
                uint32_t base = bb + (n0 + nj * 8 + g) * ROW_B + (kb + tq) * 4;
                Bf[nj][0] = lds_tf32(base);
                Bf[nj][1] = lds_tf32(base + 16);
            }

            #pragma unroll
            for (int mi = 0; mi < 2; mi++)
                #pragma unroll
                for (int nj = 0; nj < 4; nj++)
                    mma_tf32(acc[mi][nj], Af[mi], Bf[nj]);
        }
        __syncthreads();

        if (t + 2 < NBLK) CP_ISSUE(t + 2, t & 1);
    }

    // ---- epilogue: out[b, c, o] = acc / 8 ----
    const float s = 0.125f;
    #pragma unroll
    for (int mi = 0; mi < 2; mi++) {
        #pragma unroll
        for (int nj = 0; nj < 4; nj++) {
            int r0 = m0 + mi * 16 + g;
            int c0 = n0 + nj * 8 + 2 * tq;
            out[((r0    ) * COUT + c0    ) * OUT_DIM + o] = acc[mi][nj][0] * s;
            out[((r0    ) * COUT + c0 + 1) * OUT_DIM + o] = acc[mi][nj][1] * s;
            out[((r0 + 8) * COUT + c0    ) * OUT_DIM + o] = acc[mi][nj][2] * s;
            out[((r0 + 8) * COUT + c0 + 1) * OUT_DIM + o] = acc[mi][nj][3] * s;
        }
    }
}

extern "C" void kernel_launch(void* const* d_in, const int* in_sizes, int n_in,
                              void* d_out, int out_size)
{
    const float* x = (const float*)d_in[0];   // [128, 64, 1028]
    const float* w = (const float*)d_in[1];   // [1, 64, 64, 256, 8]
    float* out = (float*)d_out;               // [128, 64, 256]
    (void)in_sizes; (void)n_in; (void)out_size;

    cudaFuncSetAttribute(lc1d_tf32, cudaFuncAttributeMaxDynamicSharedMemorySize,
                         SMEM_TOTAL);
    lc1d_tf32<<<OUT_DIM, NTHREADS, SMEM_TOTAL>>>(x, w, out);
}